// round 1
// baseline (speedup 1.0000x reference)
#include <cuda_runtime.h>
#include <math.h>

// Problem constants (fixed by the reference)
#define TT   4096   // tokens = B*S
#define DD   1024   // embed dim
#define EE   16     // experts
#define CC   512    // capacity = T*2/E
#define II   4096   // expert intermediate
#define IIS  2048   // shared intermediate

// ---------------- scratch (static device globals; no allocs allowed) -------
__device__ __align__(16) float g_scores[EE * TT];            // (E,T) softmax scores
__device__ int   g_tidx[EE * CC];                            // top-k indices
__device__ float g_tw  [EE * CC];                            // top-k weights
__device__ __align__(16) float g_xg[(size_t)EE * CC * DD];   // gathered tokens  (32 MB)
__device__ __align__(16) float g_H [(size_t)EE * CC * II];   // expert hidden    (128 MB)
__device__ __align__(16) float g_Hs[(size_t)TT * IIS];       // shared hidden    (32 MB)

// ---------------- 1) gating: logits + softmax -> g_scores[e*T + t] ---------
__global__ void k_gate(const float* __restrict__ x, const float* __restrict__ gw) {
    int t = blockIdx.x;
    __shared__ float xs[DD];
    __shared__ float lg[EE];
    int tid = threadIdx.x;                 // 128 threads
    for (int k = tid; k < DD; k += 128) xs[k] = x[(size_t)t * DD + k];
    __syncthreads();
    int w = tid >> 5, lane = tid & 31;
    for (int e = w * 4; e < w * 4 + 4; e++) {
        const float* g = gw + (size_t)e * DD;
        float s = 0.f;
        for (int k = lane; k < DD; k += 32) s += xs[k] * g[k];
        for (int o = 16; o; o >>= 1) s += __shfl_down_sync(0xffffffffu, s, o);
        if (!lane) lg[e] = s;
    }
    __syncthreads();
    if (tid == 0) {
        float m = lg[0];
        for (int e = 1; e < EE; e++) m = fmaxf(m, lg[e]);
        float ex[EE]; float sum = 0.f;
        for (int e = 0; e < EE; e++) { ex[e] = expf(lg[e] - m); sum += ex[e]; }
        float inv = 1.f / sum;
        for (int e = 0; e < EE; e++) g_scores[(size_t)e * TT + t] = ex[e] * inv;
    }
}

// ---------------- 2) per-expert top-C via in-smem bitonic sort -------------
__global__ void k_topk() {
    int e = blockIdx.x;
    __shared__ float v[TT];
    __shared__ int   ix[TT];
    int tid = threadIdx.x;                 // 512 threads
    for (int i = tid; i < TT; i += 512) { v[i] = g_scores[(size_t)e * TT + i]; ix[i] = i; }
    __syncthreads();
    for (int k = 2; k <= TT; k <<= 1) {
        for (int j = k >> 1; j > 0; j >>= 1) {
            for (int i = tid; i < TT; i += 512) {
                int p = i ^ j;
                if (p > i) {
                    bool desc = ((i & k) == 0);
                    float a = v[i], b = v[p];
                    bool sw = desc ? (a < b) : (a > b);
                    if (sw) { v[i] = b; v[p] = a; int q = ix[i]; ix[i] = ix[p]; ix[p] = q; }
                }
            }
            __syncthreads();
        }
    }
    for (int c = tid; c < CC; c += 512) { g_tidx[e * CC + c] = ix[c]; g_tw[e * CC + c] = v[c]; }
}

// ---------------- 3) gather selected tokens into g_xg ---------------------
__global__ void k_gather(const float4* __restrict__ x4) {
    int gid = blockIdx.x * blockDim.x + threadIdx.x;     // E*C*D/4 = 2,097,152
    if (gid >= EE * CC * (DD / 4)) return;
    int q = gid & (DD / 4 - 1);     // 0..255
    int r = gid >> 8;               // 0..E*C-1
    int tok = g_tidx[r];
    reinterpret_cast<float4*>(g_xg)[gid] = x4[(size_t)tok * (DD / 4) + q];
}

// ---------------- 4) fused dual NT-GEMM + exact GELU gate -----------------
// H = gelu(A @ Bg^T) * (A @ Bu^T).  A:(M,K) row-major, B*:(N,K) row-major.
__global__ __launch_bounds__(256) void k_mlp_in(
    const float* __restrict__ A0, const float* __restrict__ Bg0,
    const float* __restrict__ Bu0, float* __restrict__ H0,
    int M, int N, int K, long strideA, long strideB, long strideH)
{
    int e = blockIdx.z;
    const float* A  = A0  + (size_t)e * strideA;
    const float* Bg = Bg0 + (size_t)e * strideB;
    const float* Bu = Bu0 + (size_t)e * strideB;
    float*       H  = H0  + (size_t)e * strideH;

    __shared__ __align__(16) float As[16][68];
    __shared__ __align__(16) float Gs[16][68];
    __shared__ __align__(16) float Us[16][68];

    int m0 = blockIdx.y * 64, n0 = blockIdx.x * 64;
    int tid = threadIdx.x;
    int tx = tid & 15, ty = tid >> 4;
    int lr = tid >> 2;            // load row 0..63
    int lk = (tid & 3) * 4;       // load k 0,4,8,12

    float accG[4][4] = {{0}}, accU[4][4] = {{0}};

    for (int k0 = 0; k0 < K; k0 += 16) {
        float4 a  = *(const float4*)&A [(size_t)(m0 + lr) * K + k0 + lk];
        float4 bg = *(const float4*)&Bg[(size_t)(n0 + lr) * K + k0 + lk];
        float4 bu = *(const float4*)&Bu[(size_t)(n0 + lr) * K + k0 + lk];
        As[lk + 0][lr] = a.x;  As[lk + 1][lr] = a.y;  As[lk + 2][lr] = a.z;  As[lk + 3][lr] = a.w;
        Gs[lk + 0][lr] = bg.x; Gs[lk + 1][lr] = bg.y; Gs[lk + 2][lr] = bg.z; Gs[lk + 3][lr] = bg.w;
        Us[lk + 0][lr] = bu.x; Us[lk + 1][lr] = bu.y; Us[lk + 2][lr] = bu.z; Us[lk + 3][lr] = bu.w;
        __syncthreads();
#pragma unroll
        for (int k = 0; k < 16; k++) {
            float4 av = *(const float4*)&As[k][ty * 4];
            float4 gv = *(const float4*)&Gs[k][tx * 4];
            float4 uv = *(const float4*)&Us[k][tx * 4];
            float ar[4] = {av.x, av.y, av.z, av.w};
            float gr[4] = {gv.x, gv.y, gv.z, gv.w};
            float ur[4] = {uv.x, uv.y, uv.z, uv.w};
#pragma unroll
            for (int i = 0; i < 4; i++)
#pragma unroll
                for (int j = 0; j < 4; j++) {
                    accG[i][j] = fmaf(ar[i], gr[j], accG[i][j]);
                    accU[i][j] = fmaf(ar[i], ur[j], accU[i][j]);
                }
        }
        __syncthreads();
    }
#pragma unroll
    for (int i = 0; i < 4; i++) {
        size_t row = (size_t)(m0 + ty * 4 + i) * N + n0 + tx * 4;
#pragma unroll
        for (int j = 0; j < 4; j++) {
            float g = accG[i][j];
            float h = 0.5f * g * (1.f + erff(g * 0.70710678118654752f)) * accU[i][j];
            H[row + j] = h;
        }
    }
}

// ---------------- 5) NT-GEMM down-proj, store or scaled scatter-add -------
// out_row = A @ B^T ; if tidx!=null: atomicAdd(out[tidx[m]], val*tw[m])
__global__ __launch_bounds__(256) void k_mlp_out(
    const float* __restrict__ A0, const float* __restrict__ B0,
    float* __restrict__ out, int M, int N, int K,
    long strideA, long strideB,
    const int* __restrict__ tidx, const float* __restrict__ tw)
{
    int e = blockIdx.z;
    const float* A = A0 + (size_t)e * strideA;
    const float* B = B0 + (size_t)e * strideB;

    __shared__ __align__(16) float As[16][68];
    __shared__ __align__(16) float Bs[16][68];

    int m0 = blockIdx.y * 64, n0 = blockIdx.x * 64;
    int tid = threadIdx.x;
    int tx = tid & 15, ty = tid >> 4;
    int lr = tid >> 2;
    int lk = (tid & 3) * 4;

    float acc[4][4] = {{0}};

    for (int k0 = 0; k0 < K; k0 += 16) {
        float4 a = *(const float4*)&A[(size_t)(m0 + lr) * K + k0 + lk];
        float4 b = *(const float4*)&B[(size_t)(n0 + lr) * K + k0 + lk];
        As[lk + 0][lr] = a.x; As[lk + 1][lr] = a.y; As[lk + 2][lr] = a.z; As[lk + 3][lr] = a.w;
        Bs[lk + 0][lr] = b.x; Bs[lk + 1][lr] = b.y; Bs[lk + 2][lr] = b.z; Bs[lk + 3][lr] = b.w;
        __syncthreads();
#pragma unroll
        for (int k = 0; k < 16; k++) {
            float4 av = *(const float4*)&As[k][ty * 4];
            float4 bv = *(const float4*)&Bs[k][tx * 4];
            float ar[4] = {av.x, av.y, av.z, av.w};
            float br[4] = {bv.x, bv.y, bv.z, bv.w};
#pragma unroll
            for (int i = 0; i < 4; i++)
#pragma unroll
                for (int j = 0; j < 4; j++)
                    acc[i][j] = fmaf(ar[i], br[j], acc[i][j]);
        }
        __syncthreads();
    }
    if (tidx) {
#pragma unroll
        for (int i = 0; i < 4; i++) {
            int m = m0 + ty * 4 + i;
            int tok = tidx[e * CC + m];
            float w = tw[e * CC + m];
            size_t base = (size_t)tok * N + n0 + tx * 4;
#pragma unroll
            for (int j = 0; j < 4; j++)
                atomicAdd(&out[base + j], acc[i][j] * w);
        }
    } else {
#pragma unroll
        for (int i = 0; i < 4; i++) {
            size_t base = (size_t)(m0 + ty * 4 + i) * N + n0 + tx * 4;
#pragma unroll
            for (int j = 0; j < 4; j++)
                out[base + j] = acc[i][j];
        }
    }
}

// ---------------- launch ---------------------------------------------------
extern "C" void kernel_launch(void* const* d_in, const int* in_sizes, int n_in,
                              void* d_out, int out_size) {
    const float* x  = (const float*)d_in[0];   // (B,S,D) = (T,D)
    const float* gw = (const float*)d_in[1];   // (E,D)
    const float* Wg = (const float*)d_in[2];   // (E,I,D)
    const float* Wu = (const float*)d_in[3];   // (E,I,D)
    const float* Wd = (const float*)d_in[4];   // (E,D,I)
    const float* Sg = (const float*)d_in[5];   // (IS,D)
    const float* Su = (const float*)d_in[6];   // (IS,D)
    const float* Sd = (const float*)d_in[7];   // (D,IS)
    float* out = (float*)d_out;                // (T,D)

    float *xg, *H, *Hs, *tw; int* tidx;
    cudaGetSymbolAddress((void**)&xg,   g_xg);
    cudaGetSymbolAddress((void**)&H,    g_H);
    cudaGetSymbolAddress((void**)&Hs,   g_Hs);
    cudaGetSymbolAddress((void**)&tidx, g_tidx);
    cudaGetSymbolAddress((void**)&tw,   g_tw);

    // gating + softmax
    k_gate<<<TT, 128>>>(x, gw);
    // per-expert top-C
    k_topk<<<EE, 512>>>();
    // gather tokens
    k_gather<<<(EE * CC * (DD / 4) + 255) / 256, 256>>>((const float4*)x);

    // expert gate/up + gelu-gate  (M=C, N=I, K=D), batched over experts
    dim3 g1(II / 64, CC / 64, EE);
    k_mlp_in<<<g1, 256>>>(xg, Wg, Wu, H, CC, II, DD,
                          (long)CC * DD, (long)II * DD, (long)CC * II);
    // shared gate/up + gelu-gate  (M=T, N=IS, K=D)
    dim3 g2(IIS / 64, TT / 64, 1);
    k_mlp_in<<<g2, 256>>>(x, Sg, Su, Hs, TT, IIS, DD, 0, 0, 0);

    // shared down-proj: initializes out fully  (M=T, N=D, K=IS)
    dim3 g3(DD / 64, TT / 64, 1);
    k_mlp_out<<<g3, 256>>>(Hs, Sd, out, TT, DD, IIS, 0, 0, nullptr, nullptr);
    // expert down-proj + weighted scatter-add  (M=C, N=D, K=I)
    dim3 g4(DD / 64, CC / 64, EE);
    k_mlp_out<<<g4, 256>>>(H, Wd, out, CC, DD, II,
                           (long)CC * II, (long)DD * II, tidx, tw);
}

// round 3
// speedup vs baseline: 5.2409x; 5.2409x over previous
#include <cuda_runtime.h>
#include <math.h>

// Problem constants (fixed by the reference)
#define TT   4096   // tokens = B*S
#define DD   1024   // embed dim
#define EE   16     // experts
#define CC   512    // capacity = T*2/E
#define II   4096   // expert intermediate
#define IIS  2048   // shared intermediate

#define BK   16     // k-tile (fp32 elements)
#define AST  20     // smem row stride in floats (bank-conflict-free for frag LDS)

// ---------------- scratch (static device globals; no allocs allowed) -------
__device__ __align__(16) float g_scores[EE * TT];
__device__ int   g_tidx[EE * CC];
__device__ float g_tw  [EE * CC];
__device__ __align__(16) float g_xg[(size_t)EE * CC * DD];   // gathered tokens  (32 MB)
__device__ __align__(16) float g_H [(size_t)EE * CC * II];   // expert hidden    (128 MB)
__device__ __align__(16) float g_Hs[(size_t)TT * IIS];       // shared hidden    (32 MB)

// ---------------- helpers --------------------------------------------------
__device__ __forceinline__ unsigned f2tf(float x) {
    unsigned r;
    asm("cvt.rna.tf32.f32 %0, %1;" : "=r"(r) : "f"(x));
    return r;
}

__device__ __forceinline__ void mma_tf32(float* d, const unsigned* a, const unsigned* b,
                                         const float* c) {
    asm volatile(
        "mma.sync.aligned.m16n8k8.row.col.f32.tf32.tf32.f32 "
        "{%0,%1,%2,%3},{%4,%5,%6,%7},{%8,%9},{%10,%11,%12,%13};"
        : "=f"(d[0]), "=f"(d[1]), "=f"(d[2]), "=f"(d[3])
        : "r"(a[0]), "r"(a[1]), "r"(a[2]), "r"(a[3]),
          "r"(b[0]), "r"(b[1]),
          "f"(c[0]), "f"(c[1]), "f"(c[2]), "f"(c[3]));
}

__device__ __forceinline__ void cpa16(void* dst, const void* src) {
    unsigned s = (unsigned)__cvta_generic_to_shared(dst);
    asm volatile("cp.async.cg.shared.global [%0], [%1], 16;" :: "r"(s), "l"(src));
}
__device__ __forceinline__ void cpa_commit() { asm volatile("cp.async.commit_group;"); }
__device__ __forceinline__ void cpa_wait1()  { asm volatile("cp.async.wait_group 1;"); }

__device__ __forceinline__ float gelu_exact(float g) {
    return 0.5f * g * (1.f + erff(g * 0.70710678118654752f));
}

// ---------------- 1) gating: logits + softmax ------------------------------
__global__ void k_gate(const float* __restrict__ x, const float* __restrict__ gw) {
    int t = blockIdx.x;
    __shared__ float xs[DD];
    __shared__ float lg[EE];
    int tid = threadIdx.x;                 // 128 threads
    for (int k = tid; k < DD; k += 128) xs[k] = x[(size_t)t * DD + k];
    __syncthreads();
    int w = tid >> 5, lane = tid & 31;
    for (int e = w * 4; e < w * 4 + 4; e++) {
        const float* g = gw + (size_t)e * DD;
        float s = 0.f;
        for (int k = lane; k < DD; k += 32) s += xs[k] * g[k];
        for (int o = 16; o; o >>= 1) s += __shfl_down_sync(0xffffffffu, s, o);
        if (!lane) lg[e] = s;
    }
    __syncthreads();
    if (tid == 0) {
        float m = lg[0];
        for (int e = 1; e < EE; e++) m = fmaxf(m, lg[e]);
        float ex[EE]; float sum = 0.f;
        for (int e = 0; e < EE; e++) { ex[e] = expf(lg[e] - m); sum += ex[e]; }
        float inv = 1.f / sum;
        for (int e = 0; e < EE; e++) g_scores[(size_t)e * TT + t] = ex[e] * inv;
    }
}

// ---------------- 2) per-expert top-C via bitonic sort ---------------------
__global__ void k_topk() {
    int e = blockIdx.x;
    __shared__ float v[TT];
    __shared__ int   ix[TT];
    int tid = threadIdx.x;                 // 512 threads
    for (int i = tid; i < TT; i += 512) { v[i] = g_scores[(size_t)e * TT + i]; ix[i] = i; }
    __syncthreads();
    for (int k = 2; k <= TT; k <<= 1) {
        for (int j = k >> 1; j > 0; j >>= 1) {
            for (int i = tid; i < TT; i += 512) {
                int p = i ^ j;
                if (p > i) {
                    bool desc = ((i & k) == 0);
                    float a = v[i], b = v[p];
                    bool sw = desc ? (a < b) : (a > b);
                    if (sw) { v[i] = b; v[p] = a; int q = ix[i]; ix[i] = ix[p]; ix[p] = q; }
                }
            }
            __syncthreads();
        }
    }
    for (int c = tid; c < CC; c += 512) { g_tidx[e * CC + c] = ix[c]; g_tw[e * CC + c] = v[c]; }
}

// ---------------- 3) gather selected tokens --------------------------------
__global__ void k_gather(const float4* __restrict__ x4) {
    int gid = blockIdx.x * blockDim.x + threadIdx.x;
    if (gid >= EE * CC * (DD / 4)) return;
    int q = gid & (DD / 4 - 1);
    int r = gid >> 8;
    int tok = g_tidx[r];
    reinterpret_cast<float4*>(g_xg)[gid] = x4[(size_t)tok * (DD / 4) + q];
}

// ---------------- 4) dual NT-GEMM (tf32 HMMA) + exact GELU gate ------------
// H = gelu(A @ Bg^T) * (A @ Bu^T).  A:(M,K) rm, B*:(N,K) rm.
// Block tile 128(M) x 64(N), warps 2x4, warp tile 64x16.
__global__ __launch_bounds__(256, 2) void k_mlp_in_tc(
    const float* __restrict__ A0, const float* __restrict__ Bg0,
    const float* __restrict__ Bu0, float* __restrict__ H0,
    int M, int N, int K, long sA, long sB, long sH)
{
    __shared__ float As[2][128][AST];
    __shared__ float Gs[2][64][AST];
    __shared__ float Us[2][64][AST];

    int e = blockIdx.z;
    const float* A  = A0  + (size_t)e * sA;
    const float* Bg = Bg0 + (size_t)e * sB;
    const float* Bu = Bu0 + (size_t)e * sB;
    float*       H  = H0  + (size_t)e * sH;

    int m0 = blockIdx.y * 128, n0 = blockIdx.x * 64;
    int tid = threadIdx.x, lane = tid & 31, warp = tid >> 5;
    int mo = (warp & 1) * 64, no = (warp >> 1) * 16;

    float accG[4][2][4] = {{{0}}}, accU[4][2][4] = {{{0}}};

    int ar = tid >> 2, aq = (tid & 3) * 4;   // A loader: rows 0..63 (+64), quad
    int iters = K / BK;

    // prologue: stage 0
    {
        cpa16(&As[0][ar][aq],      A  + (size_t)(m0 + ar) * K + aq);
        cpa16(&As[0][ar + 64][aq], A  + (size_t)(m0 + ar + 64) * K + aq);
        cpa16(&Gs[0][ar][aq],      Bg + (size_t)(n0 + ar) * K + aq);
        cpa16(&Us[0][ar][aq],      Bu + (size_t)(n0 + ar) * K + aq);
    }
    cpa_commit();

    for (int it = 0; it < iters; it++) {
        int st = it & 1;
        if (it + 1 < iters) {
            int ns = 1 - st;
            long k0 = (long)(it + 1) * BK;
            cpa16(&As[ns][ar][aq],      A  + (size_t)(m0 + ar) * K + k0 + aq);
            cpa16(&As[ns][ar + 64][aq], A  + (size_t)(m0 + ar + 64) * K + k0 + aq);
            cpa16(&Gs[ns][ar][aq],      Bg + (size_t)(n0 + ar) * K + k0 + aq);
            cpa16(&Us[ns][ar][aq],      Bu + (size_t)(n0 + ar) * K + k0 + aq);
        }
        cpa_commit();
        cpa_wait1();
        __syncthreads();

#pragma unroll
        for (int ks = 0; ks < BK; ks += 8) {
            unsigned af[4][4];
#pragma unroll
            for (int mi = 0; mi < 4; mi++) {
                int r = mo + mi * 16 + (lane >> 2);
                int c = ks + (lane & 3);
                af[mi][0] = f2tf(As[st][r][c]);
                af[mi][1] = f2tf(As[st][r + 8][c]);
                af[mi][2] = f2tf(As[st][r][c + 4]);
                af[mi][3] = f2tf(As[st][r + 8][c + 4]);
            }
#pragma unroll
            for (int ni = 0; ni < 2; ni++) {
                int bn = no + ni * 8 + (lane >> 2);
                int c = ks + (lane & 3);
                unsigned bg[2], bu[2];
                bg[0] = f2tf(Gs[st][bn][c]); bg[1] = f2tf(Gs[st][bn][c + 4]);
                bu[0] = f2tf(Us[st][bn][c]); bu[1] = f2tf(Us[st][bn][c + 4]);
#pragma unroll
                for (int mi = 0; mi < 4; mi++) {
                    mma_tf32(accG[mi][ni], af[mi], bg, accG[mi][ni]);
                    mma_tf32(accU[mi][ni], af[mi], bu, accU[mi][ni]);
                }
            }
        }
        __syncthreads();
    }

    // epilogue: h = gelu(g) * u
#pragma unroll
    for (int mi = 0; mi < 4; mi++) {
        int r0 = m0 + mo + mi * 16 + (lane >> 2);
#pragma unroll
        for (int ni = 0; ni < 2; ni++) {
            int col = n0 + no + ni * 8 + (lane & 3) * 2;
            float* p0 = H + (size_t)r0 * N + col;
            float* p1 = H + (size_t)(r0 + 8) * N + col;
            p0[0] = gelu_exact(accG[mi][ni][0]) * accU[mi][ni][0];
            p0[1] = gelu_exact(accG[mi][ni][1]) * accU[mi][ni][1];
            p1[0] = gelu_exact(accG[mi][ni][2]) * accU[mi][ni][2];
            p1[1] = gelu_exact(accG[mi][ni][3]) * accU[mi][ni][3];
        }
    }
}

// ---------------- 5) NT-GEMM down-proj (tf32 HMMA), store or scatter -------
// Block tile 128x128, warps 2x4, warp tile 64x32.
__global__ __launch_bounds__(256, 2) void k_mlp_out_tc(
    const float* __restrict__ A0, const float* __restrict__ B0,
    float* __restrict__ out, int M, int N, int K, long sA, long sB,
    const int* __restrict__ tidx, const float* __restrict__ tw)
{
    __shared__ float As[2][128][AST];
    __shared__ float Bs[2][128][AST];

    int e = blockIdx.z;
    const float* A = A0 + (size_t)e * sA;
    const float* B = B0 + (size_t)e * sB;

    int m0 = blockIdx.y * 128, n0 = blockIdx.x * 128;
    int tid = threadIdx.x, lane = tid & 31, warp = tid >> 5;
    int mo = (warp & 1) * 64, no = (warp >> 1) * 32;

    float acc[4][4][4] = {{{0}}};

    int ar = tid >> 2, aq = (tid & 3) * 4;
    int iters = K / BK;

    {
        cpa16(&As[0][ar][aq],      A + (size_t)(m0 + ar) * K + aq);
        cpa16(&As[0][ar + 64][aq], A + (size_t)(m0 + ar + 64) * K + aq);
        cpa16(&Bs[0][ar][aq],      B + (size_t)(n0 + ar) * K + aq);
        cpa16(&Bs[0][ar + 64][aq], B + (size_t)(n0 + ar + 64) * K + aq);
    }
    cpa_commit();

    for (int it = 0; it < iters; it++) {
        int st = it & 1;
        if (it + 1 < iters) {
            int ns = 1 - st;
            long k0 = (long)(it + 1) * BK;
            cpa16(&As[ns][ar][aq],      A + (size_t)(m0 + ar) * K + k0 + aq);
            cpa16(&As[ns][ar + 64][aq], A + (size_t)(m0 + ar + 64) * K + k0 + aq);
            cpa16(&Bs[ns][ar][aq],      B + (size_t)(n0 + ar) * K + k0 + aq);
            cpa16(&Bs[ns][ar + 64][aq], B + (size_t)(n0 + ar + 64) * K + k0 + aq);
        }
        cpa_commit();
        cpa_wait1();
        __syncthreads();

#pragma unroll
        for (int ks = 0; ks < BK; ks += 8) {
            unsigned af[4][4];
#pragma unroll
            for (int mi = 0; mi < 4; mi++) {
                int r = mo + mi * 16 + (lane >> 2);
                int c = ks + (lane & 3);
                af[mi][0] = f2tf(As[st][r][c]);
                af[mi][1] = f2tf(As[st][r + 8][c]);
                af[mi][2] = f2tf(As[st][r][c + 4]);
                af[mi][3] = f2tf(As[st][r + 8][c + 4]);
            }
#pragma unroll
            for (int ni = 0; ni < 4; ni++) {
                int bn = no + ni * 8 + (lane >> 2);
                int c = ks + (lane & 3);
                unsigned bf[2];
                bf[0] = f2tf(Bs[st][bn][c]); bf[1] = f2tf(Bs[st][bn][c + 4]);
#pragma unroll
                for (int mi = 0; mi < 4; mi++)
                    mma_tf32(acc[mi][ni], af[mi], bf, acc[mi][ni]);
            }
        }
        __syncthreads();
    }

    if (tidx) {
#pragma unroll
        for (int mi = 0; mi < 4; mi++) {
            int mA = m0 + mo + mi * 16 + (lane >> 2);
            int mB = mA + 8;
            int tokA = tidx[e * CC + mA]; float wA = tw[e * CC + mA];
            int tokB = tidx[e * CC + mB]; float wB = tw[e * CC + mB];
#pragma unroll
            for (int ni = 0; ni < 4; ni++) {
                int col = n0 + no + ni * 8 + (lane & 3) * 2;
                atomicAdd(&out[(size_t)tokA * N + col],     acc[mi][ni][0] * wA);
                atomicAdd(&out[(size_t)tokA * N + col + 1], acc[mi][ni][1] * wA);
                atomicAdd(&out[(size_t)tokB * N + col],     acc[mi][ni][2] * wB);
                atomicAdd(&out[(size_t)tokB * N + col + 1], acc[mi][ni][3] * wB);
            }
        }
    } else {
#pragma unroll
        for (int mi = 0; mi < 4; mi++) {
            int r0 = m0 + mo + mi * 16 + (lane >> 2);
#pragma unroll
            for (int ni = 0; ni < 4; ni++) {
                int col = n0 + no + ni * 8 + (lane & 3) * 2;
                float* p0 = out + (size_t)r0 * N + col;
                float* p1 = out + (size_t)(r0 + 8) * N + col;
                p0[0] = acc[mi][ni][0]; p0[1] = acc[mi][ni][1];
                p1[0] = acc[mi][ni][2]; p1[1] = acc[mi][ni][3];
            }
        }
    }
}

// ---------------- launch ---------------------------------------------------
extern "C" void kernel_launch(void* const* d_in, const int* in_sizes, int n_in,
                              void* d_out, int out_size) {
    const float* x  = (const float*)d_in[0];   // (T,D)
    const float* gw = (const float*)d_in[1];   // (E,D)
    const float* Wg = (const float*)d_in[2];   // (E,I,D)
    const float* Wu = (const float*)d_in[3];   // (E,I,D)
    const float* Wd = (const float*)d_in[4];   // (E,D,I)
    const float* Sg = (const float*)d_in[5];   // (IS,D)
    const float* Su = (const float*)d_in[6];   // (IS,D)
    const float* Sd = (const float*)d_in[7];   // (D,IS)
    float* out = (float*)d_out;                // (T,D)

    float *xg, *H, *Hs, *tw; int* tidx;
    cudaGetSymbolAddress((void**)&xg,   g_xg);
    cudaGetSymbolAddress((void**)&H,    g_H);
    cudaGetSymbolAddress((void**)&Hs,   g_Hs);
    cudaGetSymbolAddress((void**)&tidx, g_tidx);
    cudaGetSymbolAddress((void**)&tw,   g_tw);

    k_gate<<<TT, 128>>>(x, gw);
    k_topk<<<EE, 512>>>();
    k_gather<<<(EE * CC * (DD / 4) + 255) / 256, 256>>>((const float4*)x);

    // expert gate/up + gelu  (M=C, N=I, K=D) batched over experts
    dim3 g1(II / 64, CC / 128, EE);
    k_mlp_in_tc<<<g1, 256>>>(xg, Wg, Wu, H, CC, II, DD,
                             (long)CC * DD, (long)II * DD, (long)CC * II);
    // shared gate/up + gelu  (M=T, N=IS, K=D)
    dim3 g2(IIS / 64, TT / 128, 1);
    k_mlp_in_tc<<<g2, 256>>>(x, Sg, Su, Hs, TT, IIS, DD, 0, 0, 0);

    // shared down-proj: fully initializes out  (M=T, N=D, K=IS)
    dim3 g3(DD / 128, TT / 128, 1);
    k_mlp_out_tc<<<g3, 256>>>(Hs, Sd, out, TT, DD, IIS, 0, 0, nullptr, nullptr);
    // expert down-proj + weighted scatter-add  (M=C, N=D, K=I)
    dim3 g4(DD / 128, CC / 128, EE);
    k_mlp_out_tc<<<g4, 256>>>(H, Wd, out, CC, DD, II,
                              (long)CC * II, (long)DD * II, tidx, tw);
}